// round 1
// baseline (speedup 1.0000x reference)
#include <cuda_runtime.h>
#include <math.h>

// DigitalFilter: bandpass = biquad lowpass(3400Hz) -> clamp -> biquad highpass(300Hz) -> clamp
// over waveform [32, 2, 480000] f32. Parallelized via overlap-save: both IIR stages
// forget initial state within <300 samples (pole radii 0.43 and 0.92), so each chunk
// is computed independently from zero state with a 288-sample warm-up prefix.

#define T_LEN   480000
#define CHUNK   1000
#define NCHUNK  (T_LEN / CHUNK)   // 480
#define NCH     64                // 32 batch * 2 channels
#define WARM    288               // warm-up samples (32 for LP settle + 256 for HP settle)

__device__ __forceinline__ void biquad2_step(
    float xs,
    float lb0, float lb1, float lb2, float la1, float la2,
    float hb0, float hb1, float hb2, float ha1, float ha2,
    float& p1, float& p2, float& q1, float& q2, float& yo)
{
    // stage 1: lowpass, DF2T (state update uses UNclamped y1)
    float y1 = fmaf(lb0, xs, p1);
    p1 = fmaf(lb1, xs, fmaf(-la1, y1, p2));
    p2 = fmaf(lb2, xs, -la2 * y1);
    float c1 = fminf(fmaxf(y1, -1.0f), 1.0f);   // clamp between stages
    // stage 2: highpass, DF2T
    float y2 = fmaf(hb0, c1, q1);
    q1 = fmaf(hb1, c1, fmaf(-ha1, y2, q2));
    q2 = fmaf(hb2, c1, -ha2 * y2);
    yo = fminf(fmaxf(y2, -1.0f), 1.0f);         // final clamp
}

__global__ void __launch_bounds__(128)
bandpass_kernel(const float* __restrict__ x, float* __restrict__ out,
                float lb0, float lb1, float lb2, float la1, float la2,
                float hb0, float hb1, float hb2, float ha1, float ha2)
{
    int gid = blockIdx.x * blockDim.x + threadIdx.x;
    if (gid >= NCH * NCHUNK) return;

    int chan  = gid / NCHUNK;
    int chunk = gid - chan * NCHUNK;     // adjacent threads -> adjacent chunks (locality)
    int start  = chunk * CHUNK;
    int wstart = (chunk == 0) ? 0 : (start - WARM);

    const float* xin  = x   + (size_t)chan * T_LEN;
    float*       yout = out + (size_t)chan * T_LEN + start;

    float p1 = 0.f, p2 = 0.f, q1 = 0.f, q2 = 0.f;

    // wstart and start are multiples of 4 -> float4 aligned (chan stride also 16B-multiple)
    const float4* xv = (const float4*)(xin + wstart);
    int nwarm4 = (start - wstart) >> 2;   // 0 or 72
    int nmain4 = CHUNK >> 2;              // 250

    // warm-up: run the recurrence, discard output
    #pragma unroll 4
    for (int i = 0; i < nwarm4; ++i) {
        float4 v = xv[i];
        float dump;
        biquad2_step(v.x, lb0,lb1,lb2,la1,la2, hb0,hb1,hb2,ha1,ha2, p1,p2,q1,q2, dump);
        biquad2_step(v.y, lb0,lb1,lb2,la1,la2, hb0,hb1,hb2,ha1,ha2, p1,p2,q1,q2, dump);
        biquad2_step(v.z, lb0,lb1,lb2,la1,la2, hb0,hb1,hb2,ha1,ha2, p1,p2,q1,q2, dump);
        biquad2_step(v.w, lb0,lb1,lb2,la1,la2, hb0,hb1,hb2,ha1,ha2, p1,p2,q1,q2, dump);
    }

    const float4* xm = xv + nwarm4;
    float4* yv = (float4*)yout;
    #pragma unroll 2
    for (int i = 0; i < nmain4; ++i) {
        float4 v = xm[i];
        float4 o;
        biquad2_step(v.x, lb0,lb1,lb2,la1,la2, hb0,hb1,hb2,ha1,ha2, p1,p2,q1,q2, o.x);
        biquad2_step(v.y, lb0,lb1,lb2,la1,la2, hb0,hb1,hb2,ha1,ha2, p1,p2,q1,q2, o.y);
        biquad2_step(v.z, lb0,lb1,lb2,la1,la2, hb0,hb1,hb2,ha1,ha2, p1,p2,q1,q2, o.z);
        biquad2_step(v.w, lb0,lb1,lb2,la1,la2, hb0,hb1,hb2,ha1,ha2, p1,p2,q1,q2, o.w);
        yv[i] = o;
    }
}

// Host-side coefficient computation, double precision then cast to float,
// matching numpy's np.float32(c / a0) exactly.
static void biquad_coefs(double cutoff, bool lowpass, float* c)
{
    const double Q  = 0.7071067811865476;
    const double sr = 16000.0;
    double w0    = 2.0 * M_PI * cutoff / sr;
    double alpha = sin(w0) / (2.0 * Q);
    double cw    = cos(w0);
    double b0, b1, b2;
    if (lowpass) { b0 = (1.0 - cw) * 0.5; b1 =  (1.0 - cw); b2 = b0; }
    else         { b0 = (1.0 + cw) * 0.5; b1 = -(1.0 + cw); b2 = b0; }
    double a0 = 1.0 + alpha;
    double a1 = -2.0 * cw;
    double a2 = 1.0 - alpha;
    c[0] = (float)(b0 / a0);
    c[1] = (float)(b1 / a0);
    c[2] = (float)(b2 / a0);
    c[3] = (float)(a1 / a0);
    c[4] = (float)(a2 / a0);
}

extern "C" void kernel_launch(void* const* d_in, const int* in_sizes, int n_in,
                              void* d_out, int out_size)
{
    const float* x = (const float*)d_in[0];
    float* out = (float*)d_out;

    float lp[5], hp[5];
    biquad_coefs(3400.0, true,  lp);   // lowpass at max cutoff
    biquad_coefs(300.0,  false, hp);   // highpass at min cutoff

    int total = NCH * NCHUNK;          // 30720
    int block = 128;
    int grid  = (total + block - 1) / block;  // 240
    bandpass_kernel<<<grid, block>>>(x, out,
        lp[0], lp[1], lp[2], lp[3], lp[4],
        hp[0], hp[1], hp[2], hp[3], hp[4]);
}

// round 2
// speedup vs baseline: 1.2775x; 1.2775x over previous
#include <cuda_runtime.h>
#include <math.h>

// DigitalFilter: bandpass = biquad lowpass(3400Hz) -> clamp -> biquad highpass(300Hz) -> clamp
// over waveform [32, 2, 480000] f32. Overlap-save parallelization:
// highpass pole radius 0.9576 -> state forgotten to ~2.4e-4 in 192 samples;
// lowpass pole radius 0.559 -> forgotten in <40. Each chunk computed
// independently from zero state with a 192-sample warm-up prefix.
//
// R2 change vs R1: CHUNK 1000->256 (4x warps: 25/SM, was 6.5/SM) and
// WARM 288->192 (read amplification 1.29x->1.75x but mostly L2-resident).
// R1 was latency-bound (occ 9.8%, issue 13.2%, dram 24%).

#define T_LEN   480000
#define CHUNK   256
#define NCHUNK  (T_LEN / CHUNK)   // 1875
#define NCH     64                // 32 batch * 2 channels
#define WARM    192               // warm-up samples (highpass settle dominates)

__device__ __forceinline__ void biquad2_step(
    float xs,
    float lb0, float lb1, float lb2, float la1, float la2,
    float hb0, float hb1, float hb2, float ha1, float ha2,
    float& p1, float& p2, float& q1, float& q2, float& yo)
{
    // stage 1: lowpass, DF2T (state update uses UNclamped y1)
    float y1 = fmaf(lb0, xs, p1);
    p1 = fmaf(lb1, xs, fmaf(-la1, y1, p2));
    p2 = fmaf(lb2, xs, -la2 * y1);
    float c1 = fminf(fmaxf(y1, -1.0f), 1.0f);   // clamp between stages
    // stage 2: highpass, DF2T
    float y2 = fmaf(hb0, c1, q1);
    q1 = fmaf(hb1, c1, fmaf(-ha1, y2, q2));
    q2 = fmaf(hb2, c1, -ha2 * y2);
    yo = fminf(fmaxf(y2, -1.0f), 1.0f);         // final clamp
}

__global__ void __launch_bounds__(128)
bandpass_kernel(const float* __restrict__ x, float* __restrict__ out,
                float lb0, float lb1, float lb2, float la1, float la2,
                float hb0, float hb1, float hb2, float ha1, float ha2)
{
    int gid = blockIdx.x * blockDim.x + threadIdx.x;
    if (gid >= NCH * NCHUNK) return;

    int chan  = gid / NCHUNK;
    int chunk = gid - chan * NCHUNK;     // adjacent threads -> adjacent chunks (L2 locality)
    int start  = chunk * CHUNK;
    int wstart = (chunk == 0) ? 0 : (start - WARM);

    const float* xin  = x   + (size_t)chan * T_LEN;
    float*       yout = out + (size_t)chan * T_LEN + start;

    float p1 = 0.f, p2 = 0.f, q1 = 0.f, q2 = 0.f;

    // wstart and start are multiples of 64 -> float4 aligned
    const float4* xv = (const float4*)(xin + wstart);
    int nwarm4 = (start - wstart) >> 2;   // 0 or 48
    int nmain4 = CHUNK >> 2;              // 64

    // warm-up: run the recurrence, discard output
    #pragma unroll 4
    for (int i = 0; i < nwarm4; ++i) {
        float4 v = xv[i];
        float dump;
        biquad2_step(v.x, lb0,lb1,lb2,la1,la2, hb0,hb1,hb2,ha1,ha2, p1,p2,q1,q2, dump);
        biquad2_step(v.y, lb0,lb1,lb2,la1,la2, hb0,hb1,hb2,ha1,ha2, p1,p2,q1,q2, dump);
        biquad2_step(v.z, lb0,lb1,lb2,la1,la2, hb0,hb1,hb2,ha1,ha2, p1,p2,q1,q2, dump);
        biquad2_step(v.w, lb0,lb1,lb2,la1,la2, hb0,hb1,hb2,ha1,ha2, p1,p2,q1,q2, dump);
    }

    const float4* xm = xv + nwarm4;
    float4* yv = (float4*)yout;
    #pragma unroll 4
    for (int i = 0; i < nmain4; ++i) {
        float4 v = xm[i];
        float4 o;
        biquad2_step(v.x, lb0,lb1,lb2,la1,la2, hb0,hb1,hb2,ha1,ha2, p1,p2,q1,q2, o.x);
        biquad2_step(v.y, lb0,lb1,lb2,la1,la2, hb0,hb1,hb2,ha1,ha2, p1,p2,q1,q2, o.y);
        biquad2_step(v.z, lb0,lb1,lb2,la1,la2, hb0,hb1,hb2,ha1,ha2, p1,p2,q1,q2, o.z);
        biquad2_step(v.w, lb0,lb1,lb2,la1,la2, hb0,hb1,hb2,ha1,ha2, p1,p2,q1,q2, o.w);
        yv[i] = o;
    }
}

// Host-side coefficient computation, double precision then cast to float,
// matching numpy's np.float32(c / a0) exactly.
static void biquad_coefs(double cutoff, bool lowpass, float* c)
{
    const double Q  = 0.7071067811865476;
    const double sr = 16000.0;
    double w0    = 2.0 * M_PI * cutoff / sr;
    double alpha = sin(w0) / (2.0 * Q);
    double cw    = cos(w0);
    double b0, b1, b2;
    if (lowpass) { b0 = (1.0 - cw) * 0.5; b1 =  (1.0 - cw); b2 = b0; }
    else         { b0 = (1.0 + cw) * 0.5; b1 = -(1.0 + cw); b2 = b0; }
    double a0 = 1.0 + alpha;
    double a1 = -2.0 * cw;
    double a2 = 1.0 - alpha;
    c[0] = (float)(b0 / a0);
    c[1] = (float)(b1 / a0);
    c[2] = (float)(b2 / a0);
    c[3] = (float)(a1 / a0);
    c[4] = (float)(a2 / a0);
}

extern "C" void kernel_launch(void* const* d_in, const int* in_sizes, int n_in,
                              void* d_out, int out_size)
{
    const float* x = (const float*)d_in[0];
    float* out = (float*)d_out;

    float lp[5], hp[5];
    biquad_coefs(3400.0, true,  lp);   // lowpass at max cutoff
    biquad_coefs(300.0,  false, hp);   // highpass at min cutoff

    int total = NCH * NCHUNK;          // 120000
    int block = 128;
    int grid  = (total + block - 1) / block;  // 938
    bandpass_kernel<<<grid, block>>>(x, out,
        lp[0], lp[1], lp[2], lp[3], lp[4],
        hp[0], hp[1], hp[2], hp[3], hp[4]);
}